// round 1
// baseline (speedup 1.0000x reference)
#include <cuda_runtime.h>
#include <math.h>
#include <float.h>

#define B   64
#define H   224
#define W   224
#define HW  (H*W)
#define NTOT (B*HW)
#define NC  196
#define NBR 10
#define WINS 20
#define ITERS 50

// ---------------- scratch (static device globals; no runtime allocation) ----
__device__ float         g_gray[NTOT];        // 12.8 MB
__device__ float         g_wgm [NTOT];        // 12.8 MB  grad^4 * 10
__device__ float         g_cd  [4][NTOT];     // 51.4 MB  per-dir color diff * 10
__device__ float         g_dist[2][NTOT];     // 25.7 MB  ping-pong
__device__ unsigned char g_mask[2][NTOT];     //  6.4 MB  ping-pong (255 == -1)
__device__ int           g_centi[B*NC*2];

// ---------------- phase 1: gray ---------------------------------------------
__global__ void k_gray(const float* __restrict__ x) {
    int i = blockIdx.x * blockDim.x + threadIdx.x;
    if (i >= NTOT) return;
    int b = i / HW;
    int r = i - b * HW;
    const float* xb = x + (size_t)b * 3 * HW;
    float R = xb[r], G = xb[HW + r], Bv = xb[2 * HW + r];
    float t = __fadd_rn(__fmul_rn(0.2989f, R), __fmul_rn(0.587f, G));
    g_gray[i] = __fadd_rn(t, __fmul_rn(0.114f, Bv));
}

// ---------------- phase 1: sobel -> grad (to d_out) + wgm -------------------
__device__ __forceinline__ float grayAt(const float* gb, int y, int x) {
    if ((unsigned)y >= (unsigned)H || (unsigned)x >= (unsigned)W) return 0.0f;
    return gb[y * W + x];
}

__global__ void k_grad(float* __restrict__ out_grad) {
    int i = blockIdx.x * blockDim.x + threadIdx.x;
    if (i >= NTOT) return;
    int b = i / HW;
    int r = i - b * HW;
    int y = r / W, x = r - y * W;
    const float* gb = g_gray + b * HW;

    float a00 = grayAt(gb, y - 1, x - 1), a01 = grayAt(gb, y - 1, x), a02 = grayAt(gb, y - 1, x + 1);
    float a10 = grayAt(gb, y,     x - 1),                             a12 = grayAt(gb, y,     x + 1);
    float a20 = grayAt(gb, y + 1, x - 1), a21 = grayAt(gb, y + 1, x), a22 = grayAt(gb, y + 1, x + 1);

    // gx kernel: [[-1,0,1],[-2,0,2],[-1,0,1]]  (row-major tap order)
    float gx = __fadd_rn(-a00, a02);
    gx = __fadd_rn(gx, __fmul_rn(-2.0f, a10));
    gx = __fadd_rn(gx, __fmul_rn( 2.0f, a12));
    gx = __fadd_rn(gx, -a20);
    gx = __fadd_rn(gx,  a22);
    // gy kernel: [[-1,-2,-1],[0,0,0],[1,2,1]]
    float gy = __fadd_rn(-a00, __fmul_rn(-2.0f, a01));
    gy = __fadd_rn(gy, -a02);
    gy = __fadd_rn(gy,  a20);
    gy = __fadd_rn(gy, __fmul_rn(2.0f, a21));
    gy = __fadd_rn(gy,  a22);

    float s = __fadd_rn(__fadd_rn(__fmul_rn(gx, gx), __fmul_rn(gy, gy)), 1e-8f);
    float g = sqrtf(s);
    out_grad[i] = g;
    g_wgm[i] = __fmul_rn(powf(g, 4.0f), 10.0f);
}

// ---------------- phase 1: per-direction color diffs (premultiplied x10) ----
__global__ void k_cdiff(const float* __restrict__ x) {
    int i = blockIdx.x * blockDim.x + threadIdx.x;
    if (i >= NTOT) return;
    int b = i / HW;
    int r = i - b * HW;
    int y = r / W, xx = r - y * W;
    const float* xb = x + (size_t)b * 3 * HW;

    float c0 = xb[r], c1 = xb[HW + r], c2 = xb[2 * HW + r];
    int yp = (y + 1 == H) ? 0 : y + 1;
    int ym = (y == 0) ? H - 1 : y - 1;
    int xp = (xx + 1 == W) ? 0 : xx + 1;
    int xm = (xx == 0) ? W - 1 : xx - 1;
    // roll((dy,dx)) at [y,x] reads [y-dy, x-dx]:
    int nb[4];
    nb[0] = yp * W + xx;  // dir (-1,0) -> neighbor y+1
    nb[1] = ym * W + xx;  // dir ( 1,0) -> neighbor y-1
    nb[2] = y  * W + xp;  // dir (0,-1) -> neighbor x+1
    nb[3] = y  * W + xm;  // dir (0, 1) -> neighbor x-1
#pragma unroll
    for (int d = 0; d < 4; d++) {
        int n = nb[d];
        float s = __fadd_rn(__fadd_rn(fabsf(c0 - xb[n]), fabsf(c1 - xb[HW + n])),
                            fabsf(c2 - xb[2 * HW + n]));
        g_cd[d][b * HW + n - n + r] = 0.0f; // placeholder avoided below
        g_cd[d][i] = __fmul_rn(s, 10.0f);
    }
}

// ---------------- phase 2: sequential nearest-minima snap (1 warp / batch) --
__global__ void k_cents(const float* __restrict__ grad, float* __restrict__ cents_out) {
    int b = blockIdx.x;
    int lane = threadIdx.x;
    __shared__ unsigned int occ[(HW + 31) / 32];   // 1568 words
    for (int t = lane; t < (HW + 31) / 32; t += 32) occ[t] = 0u;
    __syncwarp();

    const float* gb = grad + b * HW;
    for (int k = 0; k < NC; k++) {
        int cy = 8 + 16 * (k / 14);
        int cx = 8 + 16 * (k % 14);
        int ymin = max(0, cy - NBR), ymax = min(H, cy + NBR);
        int xmin = max(0, cx - NBR), xmax = min(W, cx + NBR);
        int h = ymax - ymin, w = xmax - xmin;

        float vals[13];
        float mv = INFINITY;
#pragma unroll
        for (int t = 0; t < 13; t++) {
            int li = lane + 32 * t;
            float v = INFINITY;
            if (li < WINS * WINS) {
                int wy = li / WINS, wx = li - wy * WINS;
                if (wy < h && wx < w) v = gb[(ymin + wy) * W + (xmin + wx)];
            }
            vals[t] = v;
            mv = fminf(mv, v);
        }
#pragma unroll
        for (int o = 16; o; o >>= 1) mv = fminf(mv, __shfl_xor_sync(0xffffffffu, mv, o));

        int best = WINS * WINS;
#pragma unroll
        for (int t = 0; t < 13; t++) {
            int li = lane + 32 * t;
            if (li < WINS * WINS && vals[t] == mv) {
                int wy = li / WINS, wx = li - wy * WINS;
                int bi = (ymin + wy) * W + (xmin + wx);
                if (!((occ[bi >> 5] >> (bi & 31)) & 1u)) best = min(best, li);
            }
        }
#pragma unroll
        for (int o = 16; o; o >>= 1) best = min(best, __shfl_xor_sync(0xffffffffu, best, o));

        int ny = cy, nx = cx;
        if (best < WINS * WINS) {
            ny = ymin + best / WINS;
            nx = xmin + best % WINS;
        }
        if (lane == 0) {
            if (best < WINS * WINS) {
                int bi = ny * W + nx;
                occ[bi >> 5] |= (1u << (bi & 31));
            }
            cents_out[(b * NC + k) * 2 + 0] = (float)ny;
            cents_out[(b * NC + k) * 2 + 1] = (float)nx;
            g_centi[(b * NC + k) * 2 + 0] = ny;
            g_centi[(b * NC + k) * 2 + 1] = nx;
        }
        __syncwarp();
    }
}

// ---------------- phase 3: init + scatter ------------------------------------
__global__ void k_init() {
    int i = blockIdx.x * blockDim.x + threadIdx.x;
    if (i >= NTOT) return;
    g_dist[0][i] = INFINITY;
    g_mask[0][i] = 255;
}

__global__ void k_scatter() {
    int b = threadIdx.x;
    if (b >= B) return;
    for (int k = 0; k < NC; k++) {
        int ny = g_centi[(b * NC + k) * 2 + 0];
        int nx = g_centi[(b * NC + k) * 2 + 1];
        int idx = b * HW + ny * W + nx;
        g_dist[0][idx] = 0.0f;
        g_mask[0][idx] = (unsigned char)k;
    }
}

// ---------------- phase 3: one directional Jacobi pass -----------------------
template <int D>
__global__ void k_pass(int s) {
    int i = blockIdx.x * blockDim.x + threadIdx.x;
    if (i >= NTOT) return;
    const float*         ds = g_dist[s];
    const unsigned char* ms = g_mask[s];
    float*               dd = g_dist[s ^ 1];
    unsigned char*       md = g_mask[s ^ 1];

    int r = i % HW;
    int y = r / W;
    int x = r - y * W;
    int n;
    if (D == 0) n = (y == H - 1) ? i - (H - 1) * W : i + W;   // read y+1 (wrap)
    if (D == 1) n = (y == 0)     ? i + (H - 1) * W : i - W;   // read y-1 (wrap)
    if (D == 2) n = (x == W - 1) ? i - (W - 1)     : i + 1;   // read x+1 (wrap)
    if (D == 3) n = (x == 0)     ? i + (W - 1)     : i - 1;   // read x-1 (wrap)

    float wd = __fadd_rn(__fadd_rn(ds[n], g_wgm[i]), g_cd[D][i]);
    float d0 = ds[i];
    bool u = wd < d0;
    dd[i] = u ? wd : d0;
    md[i] = u ? ms[n] : ms[i];
}

// ---------------- final: mask -> float output --------------------------------
__global__ void k_final(int s, float* __restrict__ out_mask) {
    int i = blockIdx.x * blockDim.x + threadIdx.x;
    if (i >= NTOT) return;
    unsigned char m = g_mask[s][i];
    out_mask[i] = (m == 255) ? -1.0f : (float)m;
}

// ---------------- launch ------------------------------------------------------
extern "C" void kernel_launch(void* const* d_in, const int* in_sizes, int n_in,
                              void* d_out, int out_size) {
    const float* x = (const float*)d_in[0];
    float* out = (float*)d_out;
    float* out_grad  = out;                       // (B,1,H,W)
    float* out_cents = out + NTOT;                // (B,196,2)
    float* out_mask  = out + NTOT + B * NC * 2;   // (B,H,W)

    const int T = 256;
    const int G = (NTOT + T - 1) / T;

    k_gray <<<G, T>>>(x);
    k_grad <<<G, T>>>(out_grad);
    k_cdiff<<<G, T>>>(x);
    k_cents<<<B, 32>>>(out_grad, out_cents);
    k_init <<<G, T>>>();
    k_scatter<<<1, 64>>>();

    int s = 0;
    for (int it = 0; it < ITERS; it++) {
        k_pass<0><<<G, T>>>(s); s ^= 1;
        k_pass<1><<<G, T>>>(s); s ^= 1;
        k_pass<2><<<G, T>>>(s); s ^= 1;
        k_pass<3><<<G, T>>>(s); s ^= 1;
    }
    k_final<<<G, T>>>(s, out_mask);
}

// round 2
// speedup vs baseline: 1.6393x; 1.6393x over previous
#include <cuda_runtime.h>
#include <math.h>
#include <float.h>

#define B    64
#define H    224
#define W    224
#define HW   (H*W)
#define NTOT (B*HW)
#define NC   196
#define NBR  10
#define WINS 20
#define ITERS 50

#define TILE   32
#define HALO   8            // supports 8 directional passes = 2 iterations
#define REG    48           // TILE + 2*HALO
#define RPX    (REG*REG)    // 2304
#define TPB    256
#define PXPT   (RPX/TPB)    // 9
#define NKER   (ITERS/2)    // 25 propagation kernels

// ---------------- scratch (static device globals) ---------------------------
__device__ float         g_gray[NTOT];
__device__ float         g_wgm [NTOT];
__device__ float         g_wcd [4][NTOT];     // wgm + 10*cdiff[d]
__device__ float         g_dist[2][NTOT];
__device__ unsigned char g_mask[2][NTOT];
__device__ int           g_centi[B*NC*2];

// ---------------- phase 1: gray ----------------------------------------------
__global__ void k_gray(const float* __restrict__ x) {
    int i = blockIdx.x * blockDim.x + threadIdx.x;
    if (i >= NTOT) return;
    int b = i / HW;
    int r = i - b * HW;
    const float* xb = x + (size_t)b * 3 * HW;
    float R = xb[r], G = xb[HW + r], Bv = xb[2 * HW + r];
    float t = __fadd_rn(__fmul_rn(0.2989f, R), __fmul_rn(0.587f, G));
    g_gray[i] = __fadd_rn(t, __fmul_rn(0.114f, Bv));
}

// ---------------- phase 1: sobel -> grad + wgm -------------------------------
__device__ __forceinline__ float grayAt(const float* gb, int y, int x) {
    if ((unsigned)y >= (unsigned)H || (unsigned)x >= (unsigned)W) return 0.0f;
    return gb[y * W + x];
}

__global__ void k_grad(float* __restrict__ out_grad) {
    int i = blockIdx.x * blockDim.x + threadIdx.x;
    if (i >= NTOT) return;
    int b = i / HW;
    int r = i - b * HW;
    int y = r / W, x = r - y * W;
    const float* gb = g_gray + b * HW;

    float a00 = grayAt(gb, y - 1, x - 1), a01 = grayAt(gb, y - 1, x), a02 = grayAt(gb, y - 1, x + 1);
    float a10 = grayAt(gb, y,     x - 1),                             a12 = grayAt(gb, y,     x + 1);
    float a20 = grayAt(gb, y + 1, x - 1), a21 = grayAt(gb, y + 1, x), a22 = grayAt(gb, y + 1, x + 1);

    float gx = __fadd_rn(-a00, a02);
    gx = __fadd_rn(gx, __fmul_rn(-2.0f, a10));
    gx = __fadd_rn(gx, __fmul_rn( 2.0f, a12));
    gx = __fadd_rn(gx, -a20);
    gx = __fadd_rn(gx,  a22);
    float gy = __fadd_rn(-a00, __fmul_rn(-2.0f, a01));
    gy = __fadd_rn(gy, -a02);
    gy = __fadd_rn(gy,  a20);
    gy = __fadd_rn(gy, __fmul_rn(2.0f, a21));
    gy = __fadd_rn(gy,  a22);

    float s = __fadd_rn(__fadd_rn(__fmul_rn(gx, gx), __fmul_rn(gy, gy)), 1e-8f);
    float g = sqrtf(s);
    out_grad[i] = g;
    g_wgm[i] = __fmul_rn(powf(g, 4.0f), 10.0f);
}

// ---------------- phase 1: fused cost maps wcd[d] = wgm + 10*cdiff[d] --------
__global__ void k_wcd(const float* __restrict__ x) {
    int i = blockIdx.x * blockDim.x + threadIdx.x;
    if (i >= NTOT) return;
    int b = i / HW;
    int r = i - b * HW;
    int y = r / W, xx = r - y * W;
    const float* xb = x + (size_t)b * 3 * HW;

    float c0 = xb[r], c1 = xb[HW + r], c2 = xb[2 * HW + r];
    int yp = (y + 1 == H) ? 0 : y + 1;
    int ym = (y == 0) ? H - 1 : y - 1;
    int xp = (xx + 1 == W) ? 0 : xx + 1;
    int xm = (xx == 0) ? W - 1 : xx - 1;
    int nb[4];
    nb[0] = yp * W + xx;  // dir (-1,0) -> neighbor y+1
    nb[1] = ym * W + xx;  // dir ( 1,0) -> neighbor y-1
    nb[2] = y  * W + xp;  // dir (0,-1) -> neighbor x+1
    nb[3] = y  * W + xm;  // dir (0, 1) -> neighbor x-1
    float w = g_wgm[i];
#pragma unroll
    for (int d = 0; d < 4; d++) {
        int n = nb[d];
        float s = __fadd_rn(__fadd_rn(fabsf(c0 - xb[n]), fabsf(c1 - xb[HW + n])),
                            fabsf(c2 - xb[2 * HW + n]));
        g_wcd[d][i] = __fadd_rn(w, __fmul_rn(s, 10.0f));
    }
}

// ---------------- phase 2: nearest-minima snap, full image in smem ----------
#define OCCW ((HW + 31) / 32)

__global__ void k_cents(const float* __restrict__ grad, float* __restrict__ cents_out) {
    extern __shared__ unsigned char smraw[];
    float*        sg  = (float*)smraw;
    unsigned int* occ = (unsigned int*)(smraw + (size_t)HW * sizeof(float));

    int b = blockIdx.x;
    int tid = threadIdx.x;
    const float* gb = grad + b * HW;
    for (int i = tid; i < HW; i += TPB) sg[i] = gb[i];
    for (int i = tid; i < OCCW; i += TPB) occ[i] = 0u;
    __syncthreads();
    if (tid >= 32) return;
    int lane = tid;

    for (int k = 0; k < NC; k++) {
        int cy = 8 + 16 * (k / 14);
        int cx = 8 + 16 * (k % 14);
        int ymin = max(0, cy - NBR), ymax = min(H, cy + NBR);
        int xmin = max(0, cx - NBR), xmax = min(W, cx + NBR);
        int h = ymax - ymin, w = xmax - xmin;

        float vals[13];
        float mv = INFINITY;
#pragma unroll
        for (int t = 0; t < 13; t++) {
            int li = lane + 32 * t;
            float v = INFINITY;
            if (li < WINS * WINS) {
                int wy = li / WINS, wx = li - wy * WINS;
                if (wy < h && wx < w) v = sg[(ymin + wy) * W + (xmin + wx)];
            }
            vals[t] = v;
            mv = fminf(mv, v);
        }
#pragma unroll
        for (int o = 16; o; o >>= 1) mv = fminf(mv, __shfl_xor_sync(0xffffffffu, mv, o));

        int best = WINS * WINS;
#pragma unroll
        for (int t = 0; t < 13; t++) {
            int li = lane + 32 * t;
            if (li < WINS * WINS && vals[t] == mv) {
                int wy = li / WINS, wx = li - wy * WINS;
                int bi = (ymin + wy) * W + (xmin + wx);
                if (!((occ[bi >> 5] >> (bi & 31)) & 1u)) best = min(best, li);
            }
        }
#pragma unroll
        for (int o = 16; o; o >>= 1) best = min(best, __shfl_xor_sync(0xffffffffu, best, o));

        int ny = cy, nx = cx;
        if (best < WINS * WINS) {
            ny = ymin + best / WINS;
            nx = xmin + best % WINS;
        }
        if (lane == 0) {
            if (best < WINS * WINS) {
                int bi = ny * W + nx;
                occ[bi >> 5] |= (1u << (bi & 31));
            }
            cents_out[(b * NC + k) * 2 + 0] = (float)ny;
            cents_out[(b * NC + k) * 2 + 1] = (float)nx;
            g_centi[(b * NC + k) * 2 + 0] = ny;
            g_centi[(b * NC + k) * 2 + 1] = nx;
        }
        __syncwarp();
    }
}

// ---------------- phase 3: init + scatter ------------------------------------
__global__ void k_init() {
    int i = blockIdx.x * blockDim.x + threadIdx.x;
    if (i >= NTOT) return;
    g_dist[0][i] = INFINITY;
    g_mask[0][i] = 255;
}

__global__ void k_scatter() {
    int b = threadIdx.x;
    if (b >= B) return;
    for (int k = 0; k < NC; k++) {
        int ny = g_centi[(b * NC + k) * 2 + 0];
        int nx = g_centi[(b * NC + k) * 2 + 1];
        int idx = b * HW + ny * W + nx;
        g_dist[0][idx] = 0.0f;
        g_mask[0][idx] = (unsigned char)k;
    }
}

// ---------------- phase 3: fused tile kernel, 2 iterations (8 passes) --------
__global__ __launch_bounds__(TPB) void k_prop(int s) {
    __shared__ float         sD[RPX];
    __shared__ unsigned char sM[RPX];
    __shared__ float         sWc[4][RPX];

    const int tid = threadIdx.x;
    const int b  = blockIdx.z;
    const int oy = blockIdx.y * TILE;
    const int ox = blockIdx.x * TILE;

    const float*         dIn  = g_dist[s];
    const unsigned char* mIn  = g_mask[s];
    float*               dOut = g_dist[s ^ 1];
    unsigned char*       mOut = g_mask[s ^ 1];

    int   lyA[PXPT], lxA[PXPT], gIdx[PXPT];
    float regD[PXPT];
    int   regM[PXPT];

#pragma unroll
    for (int p = 0; p < PXPT; p++) {
        int idx = tid + p * TPB;
        int ly = idx / REG, lx = idx - ly * REG;
        lyA[p] = ly; lxA[p] = lx;
        int gy = oy - HALO + ly; gy += (gy < 0) ? H : 0; gy -= (gy >= H) ? H : 0;
        int gx = ox - HALO + lx; gx += (gx < 0) ? W : 0; gx -= (gx >= W) ? W : 0;
        int gi = b * HW + gy * W + gx;
        gIdx[p] = gi;
        float d0 = dIn[gi];
        int   m0 = mIn[gi];
        regD[p] = d0; regM[p] = m0;
        sD[idx] = d0;
        sM[idx] = (unsigned char)m0;
        sWc[0][idx] = g_wcd[0][gi];
        sWc[1][idx] = g_wcd[1][gi];
        sWc[2][idx] = g_wcd[2][gi];
        sWc[3][idx] = g_wcd[3][gi];
    }
    __syncthreads();

#pragma unroll
    for (int pass = 0; pass < 8; pass++) {
        const int d = pass & 3;
        float nd[PXPT];
        int   nm[PXPT];
        bool  ch[PXPT];
#pragma unroll
        for (int p = 0; p < PXPT; p++) {
            int idx = tid + p * TPB;
            int ly = lyA[p], lx = lxA[p];
            bool ok; int nb;
            if (d == 0) { ok = (ly < REG - 1); nb = idx + REG; }
            else if (d == 1) { ok = (ly > 0); nb = idx - REG; }
            else if (d == 2) { ok = (lx < REG - 1); nb = idx + 1; }
            else             { ok = (lx > 0); nb = idx - 1; }
            ch[p] = false;
            if (ok) {
                float wd = __fadd_rn(sD[nb], sWc[d][idx]);
                if (wd < regD[p]) { nd[p] = wd; nm[p] = sM[nb]; ch[p] = true; }
            }
        }
        __syncthreads();
#pragma unroll
        for (int p = 0; p < PXPT; p++) {
            if (ch[p]) {
                int idx = tid + p * TPB;
                regD[p] = nd[p]; regM[p] = nm[p];
                sD[idx] = nd[p]; sM[idx] = (unsigned char)nm[p];
            }
        }
        __syncthreads();
    }

    // store central TILE x TILE
#pragma unroll
    for (int p = 0; p < PXPT; p++) {
        int ly = lyA[p], lx = lxA[p];
        if (ly >= HALO && ly < HALO + TILE && lx >= HALO && lx < HALO + TILE) {
            dOut[gIdx[p]] = regD[p];
            mOut[gIdx[p]] = (unsigned char)regM[p];
        }
    }
}

// ---------------- final: mask -> float output --------------------------------
__global__ void k_final(int s, float* __restrict__ out_mask) {
    int i = blockIdx.x * blockDim.x + threadIdx.x;
    if (i >= NTOT) return;
    unsigned char m = g_mask[s][i];
    out_mask[i] = (m == 255) ? -1.0f : (float)m;
}

// ---------------- launch ------------------------------------------------------
extern "C" void kernel_launch(void* const* d_in, const int* in_sizes, int n_in,
                              void* d_out, int out_size) {
    const float* x = (const float*)d_in[0];
    float* out = (float*)d_out;
    float* out_grad  = out;                       // (B,1,H,W)
    float* out_cents = out + NTOT;                // (B,196,2)
    float* out_mask  = out + NTOT + B * NC * 2;   // (B,H,W)

    const int T = 256;
    const int G = (NTOT + T - 1) / T;

    // opt-in to large dynamic smem for k_cents (executes immediately; not a
    // stream op, safe under graph capture; no allocation)
    static const size_t centsSmem = (size_t)HW * sizeof(float) + (size_t)OCCW * sizeof(unsigned int);
    cudaFuncSetAttribute(k_cents, cudaFuncAttributeMaxDynamicSharedMemorySize, (int)centsSmem);

    k_gray <<<G, T>>>(x);
    k_grad <<<G, T>>>(out_grad);
    k_wcd  <<<G, T>>>(x);
    k_cents<<<B, TPB, centsSmem>>>(out_grad, out_cents);
    k_init <<<G, T>>>();
    k_scatter<<<1, 64>>>();

    dim3 pg(W / TILE, H / TILE, B);
    for (int k = 0; k < NKER; k++) {
        k_prop<<<pg, TPB>>>(k & 1);
    }
    k_final<<<G, T>>>(NKER & 1, out_mask);
}